// round 5
// baseline (speedup 1.0000x reference)
#include <cuda_runtime.h>
#include <math.h>
#include <float.h>

#define BB 8
#define NN 4096
#define NP (NN / 2)  // element pairs

static __device__ __constant__ float kEPS = 1e-5f;
static __device__ __constant__ float kF2  = 2.8853900817779268f; // FACT * log2(e)
#define SKIP_LOG2 35.0f

// Scratch (device globals; no allocation allowed)
__device__ float g_pcn[BB][3][NN];
__device__ float g_dist[BB][NN];

typedef unsigned long long u64;

__device__ __forceinline__ float frcp(float x) {
    float r; asm("rcp.approx.f32 %0, %1;" : "=f"(r) : "f"(x)); return r;
}
__device__ __forceinline__ float fex2(float x) {
    float r; asm("ex2.approx.f32 %0, %1;" : "=f"(r) : "f"(x)); return r;
}
__device__ __forceinline__ u64 pk2(float lo, float hi) {
    u64 r; asm("mov.b64 %0, {%1, %2};" : "=l"(r) : "f"(lo), "f"(hi)); return r;
}
__device__ __forceinline__ void upk2(u64 v, float& lo, float& hi) {
    asm("mov.b64 {%0, %1}, %2;" : "=f"(lo), "=f"(hi) : "l"(v));
}
__device__ __forceinline__ u64 fma2(u64 a, u64 b, u64 c) {
    u64 d; asm("fma.rn.f32x2 %0, %1, %2, %3;" : "=l"(d) : "l"(a), "l"(b), "l"(c)); return d;
}
__device__ __forceinline__ u64 add2(u64 a, u64 b) {
    u64 d; asm("add.rn.f32x2 %0, %1, %2;" : "=l"(d) : "l"(a), "l"(b)); return d;
}

// ---------------------------------------------------------------------------
// Kernel 1: rows — SINGLE PASS online softmax. 4 rows/warp, 32 rows/CTA.
// Warp-uniform running (dmin, c, thr) per row. Hot loop: distance + compare
// + one vote. Rare hot iteration: warp-min reduce, uniform rescale, exp+acc.
// Monotone threshold => accumulated set is a superset of the final-threshold
// set; skipped tail mass <= NN * 2^-35 (negligible vs 1e-3 tol).
// ---------------------------------------------------------------------------
__global__ void __launch_bounds__(256, 2)
cpnet_rows(const float* __restrict__ pc1, const float* __restrict__ pc2) {
    extern __shared__ ulonglong2 smem[];
    ulonglong2* sXY = smem;        // {pk2(x0,x1), pk2(y0,y1)} : 32KB
    ulonglong2* sZR = smem + NP;   // {pk2(z0,z1), pk2(r0,r1)} : 32KB
    const int b = blockIdx.y;
    const float* p2 = pc2 + (size_t)b * 4 * NN;
    const float* p1 = pc1 + (size_t)b * 4 * NN;

    {
        const float2* px = (const float2*)p2;
        const float2* py = (const float2*)(p2 + NN);
        const float2* pz = (const float2*)(p2 + 2 * NN);
        for (int i = threadIdx.x; i < NP; i += blockDim.x) {
            float2 x = px[i], y = py[i], z = pz[i];
            float r0 = fmaf(z.x, z.x, fmaf(y.x, y.x, x.x * x.x));
            float r1 = fmaf(z.y, z.y, fmaf(y.y, y.y, x.y * x.y));
            sXY[i] = make_ulonglong2(pk2(x.x, x.y), pk2(y.x, y.y));
            sZR[i] = make_ulonglong2(pk2(z.x, z.y), pk2(r0, r1));
        }
    }
    __syncthreads();

    const int warp = threadIdx.x >> 5;
    const int lane = threadIdx.x & 31;
    const int n0 = (blockIdx.x << 5) + (warp << 2);

    float qx[4], qy[4], qz[4];
    u64 nx2[4], ny2[4], nz2[4], rp2[4];
    #pragma unroll
    for (int r = 0; r < 4; ++r) {
        qx[r] = p1[n0 + r];
        qy[r] = p1[NN + n0 + r];
        qz[r] = p1[2 * NN + n0 + r];
        float rr = fmaf(qz[r], qz[r], fmaf(qy[r], qy[r], qx[r] * qx[r]));
        nx2[r] = pk2(-2.f * qx[r], -2.f * qx[r]);
        ny2[r] = pk2(-2.f * qy[r], -2.f * qy[r]);
        nz2[r] = pk2(-2.f * qz[r], -2.f * qz[r]);
        rp2[r] = pk2(rr, rr);
    }

    const u64 F2p = pk2(kF2, kF2);
    float dm[4]  = {FLT_MAX, FLT_MAX, FLT_MAX, FLT_MAX};
    float cc[4]  = {0.f, 0.f, 0.f, 0.f};        // running softmax max (log2)
    float thr[4] = {FLT_MAX, FLT_MAX, FLT_MAX, FLT_MAX};
    u64 nc2[4]   = {0, 0, 0, 0};
    u64 Zk[4] = {0, 0, 0, 0}, ax[4] = {0, 0, 0, 0};
    u64 ay[4] = {0, 0, 0, 0}, az[4] = {0, 0, 0, 0};

    for (int p = lane; p < NP; p += 32) {
        ulonglong2 xy = sXY[p];
        ulonglong2 zr = sZR[p];
        float dlo[4], dhi[4], mrow[4];
        bool f = false;
        #pragma unroll
        for (int r = 0; r < 4; ++r) {
            u64 d = fma2(nz2[r], zr.x, fma2(ny2[r], xy.y,
                         fma2(nx2[r], xy.x, add2(zr.y, rp2[r]))));
            upk2(d, dlo[r], dhi[r]);
            mrow[r] = fminf(dlo[r], dhi[r]);
            f |= (mrow[r] <= thr[r]);
        }
        if (__any_sync(0xffffffffu, f)) {
            #pragma unroll
            for (int r = 0; r < 4; ++r) {
                // online min update (warp-uniform)
                if (__any_sync(0xffffffffu, mrow[r] < dm[r])) {
                    float m = mrow[r];
                    #pragma unroll
                    for (int o = 16; o; o >>= 1)
                        m = fminf(m, __shfl_xor_sync(0xffffffffu, m, o));
                    if (m < dm[r]) {
                        dm[r] = m;
                        float cn = kF2 * frcp(fmaxf(m, kEPS));
                        float s = fex2(cc[r] - cn);   // rescale old mass
                        u64 s2 = pk2(s, s);
                        u64 z0 = 0;
                        Zk[r] = fma2(Zk[r], s2, z0);
                        ax[r] = fma2(ax[r], s2, z0);
                        ay[r] = fma2(ay[r], s2, z0);
                        az[r] = fma2(az[r], s2, z0);
                        cc[r] = cn;
                        nc2[r] = pk2(-cn, -cn);
                        thr[r] = (cn > SKIP_LOG2) ? kF2 * frcp(cn - SKIP_LOG2)
                                                  : FLT_MAX;
                    }
                }
                // accumulate this iteration's 2 elements for row r
                float i0 = frcp(fmaxf(dlo[r], kEPS));
                float i1 = frcp(fmaxf(dhi[r], kEPS));
                u64 arg = fma2(pk2(i0, i1), F2p, nc2[r]);
                float g0, g1; upk2(arg, g0, g1);
                u64 w = pk2(fex2(g0), fex2(g1));
                Zk[r] = add2(Zk[r], w);
                ax[r] = fma2(w, xy.x, ax[r]);
                ay[r] = fma2(w, xy.y, ay[r]);
                az[r] = fma2(w, zr.x, az[r]);
            }
        }
    }

    // lane combine (cc is warp-uniform -> plain sums)
    float Zs[4], vx[4], vy[4], vz[4];
    #pragma unroll
    for (int r = 0; r < 4; ++r) {
        float lo, hi;
        upk2(Zk[r], lo, hi); Zs[r] = lo + hi;
        upk2(ax[r], lo, hi); vx[r] = lo + hi;
        upk2(ay[r], lo, hi); vy[r] = lo + hi;
        upk2(az[r], lo, hi); vz[r] = lo + hi;
    }
    #pragma unroll
    for (int o = 16; o; o >>= 1) {
        #pragma unroll
        for (int r = 0; r < 4; ++r) {
            Zs[r] += __shfl_xor_sync(0xffffffffu, Zs[r], o);
            vx[r] += __shfl_xor_sync(0xffffffffu, vx[r], o);
            vy[r] += __shfl_xor_sync(0xffffffffu, vy[r], o);
            vz[r] += __shfl_xor_sync(0xffffffffu, vz[r], o);
        }
    }

    if (lane == 0) {
        #pragma unroll
        for (int r = 0; r < 4; ++r) {
            float rz = 1.0f / Zs[r];
            float q0 = vx[r] * rz, q1 = vy[r] * rz, q2 = vz[r] * rz;
            float dx = qx[r] - q0, dy = qy[r] - q1, dz = qz[r] - q2;
            g_pcn[b][0][n0 + r] = q0;
            g_pcn[b][1][n0 + r] = q1;
            g_pcn[b][2][n0 + r] = q2;
            g_dist[b][n0 + r] = sqrtf(dx * dx + dy * dy + dz * dz);
        }
    }
}

// ---------------------------------------------------------------------------
// Kernel 2: finalize — dist mean, moments, SVD, outputs. One CTA per batch.
// ---------------------------------------------------------------------------
#define FTH 512

__global__ void __launch_bounds__(FTH)
cpnet_finalize(const float* __restrict__ pc1, float* __restrict__ out) {
    const int b = blockIdx.x;
    const float* p1 = pc1 + (size_t)b * 4 * NN;
    const int tid = threadIdx.x;
    const int lane = tid & 31;
    const int w = tid >> 5;  // 16 warps

    __shared__ double smMean[16];
    __shared__ float  smP[16][16];
    __shared__ double smS[16];

    // ---- mean dist (double partials) ----
    double sd = 0.0;
    #pragma unroll
    for (int k = 0; k < NN / FTH; ++k) sd += (double)g_dist[b][k * FTH + tid];
    #pragma unroll
    for (int o = 16; o; o >>= 1) sd += __shfl_xor_sync(0xffffffffu, sd, o);
    if (lane == 0) smMean[w] = sd;
    __syncthreads();
    double ms = 0.0;
    #pragma unroll
    for (int i = 0; i < 16; ++i) ms += smMean[i];
    const float mean = (float)(ms * (1.0 / (double)NN));

    // ---- 16 uncentered moments ----
    float P[16];
    #pragma unroll
    for (int i = 0; i < 16; ++i) P[i] = 0.f;
    #pragma unroll
    for (int k = 0; k < NN / FTH; ++k) {
        int n = k * FTH + tid;
        float dist = g_dist[b][n];
        float z = (dist - mean - kEPS) * 1e10f;
        float ind = 1.0f / (1.0f + __expf(z));
        float axx = p1[n], ayy = p1[NN + n], azz = p1[2 * NN + n];
        float bx = g_pcn[b][0][n], by = g_pcn[b][1][n], bz = g_pcn[b][2][n];
        float iax = ind * axx, iay = ind * ayy, iaz = ind * azz;
        P[0] += ind;
        P[1] += iax; P[2] += iay; P[3] += iaz;
        P[4] += ind * bx; P[5] += ind * by; P[6] += ind * bz;
        P[7]  += iax * bx; P[8]  += iax * by; P[9]  += iax * bz;
        P[10] += iay * bx; P[11] += iay * by; P[12] += iay * bz;
        P[13] += iaz * bx; P[14] += iaz * by; P[15] += iaz * bz;
    }
    #pragma unroll
    for (int o = 16; o; o >>= 1)
        #pragma unroll
        for (int i = 0; i < 16; ++i)
            P[i] += __shfl_xor_sync(0xffffffffu, P[i], o);
    if (lane == 0) {
        #pragma unroll
        for (int i = 0; i < 16; ++i) smP[w][i] = P[i];
    }
    __syncthreads();
    if (w == 0 && lane < 16) {
        double s = 0.0;
        #pragma unroll
        for (int ww = 0; ww < 16; ++ww) s += (double)smP[ww][lane];
        smS[lane] = s;
    }
    __syncthreads();

    if (tid == 0) {
        double S[16];
        #pragma unroll
        for (int i = 0; i < 16; ++i) S[i] = smS[i];

        const double sw = S[0];
        const double inv_sw = 1.0 / sw;
        float c1v[3] = {(float)(S[1] * inv_sw), (float)(S[2] * inv_sw), (float)(S[3] * inv_sw)};
        float c2v[3] = {(float)(S[4] * inv_sw), (float)(S[5] * inv_sw), (float)(S[6] * inv_sw)};
        float H[3][3];
        #pragma unroll
        for (int i = 0; i < 3; ++i)
            #pragma unroll
            for (int j = 0; j < 3; ++j)
                H[i][j] = (float)(S[7 + i * 3 + j] - S[1 + i] * S[4 + j] * inv_sw);

        float G[3][3];
        #pragma unroll
        for (int i = 0; i < 3; ++i)
            #pragma unroll
            for (int j = 0; j < 3; ++j)
                G[i][j] = H[0][i] * H[0][j] + H[1][i] * H[1][j] + H[2][i] * H[2][j];
        float V[3][3] = {{1, 0, 0}, {0, 1, 0}, {0, 0, 1}};
        const int PP[3] = {0, 0, 1}, QQ[3] = {1, 2, 2};
        #pragma unroll
        for (int it = 0; it < 18; ++it) {
            int p = PP[it % 3], q = QQ[it % 3];
            float apq = G[p][q];
            if (fabsf(apq) > 1e-25f) {
                float theta = (G[q][q] - G[p][p]) / (2.0f * apq);
                float t = copysignf(1.0f, theta) / (fabsf(theta) + sqrtf(theta * theta + 1.0f));
                float c = rsqrtf(t * t + 1.0f);
                float sn = t * c;
                #pragma unroll
                for (int k = 0; k < 3; ++k) {
                    float gkp = G[k][p], gkq = G[k][q];
                    G[k][p] = c * gkp - sn * gkq;
                    G[k][q] = sn * gkp + c * gkq;
                }
                #pragma unroll
                for (int k = 0; k < 3; ++k) {
                    float gpk = G[p][k], gqk = G[q][k];
                    G[p][k] = c * gpk - sn * gqk;
                    G[q][k] = sn * gpk + c * gqk;
                }
                #pragma unroll
                for (int k = 0; k < 3; ++k) {
                    float vkp = V[k][p], vkq = V[k][q];
                    V[k][p] = c * vkp - sn * vkq;
                    V[k][q] = sn * vkp + c * vkq;
                }
            }
        }
        float ev[3] = {G[0][0], G[1][1], G[2][2]};
        #pragma unroll
        for (int a = 0; a < 2; ++a)
            #pragma unroll
            for (int bc = 1; bc < 3; ++bc)
                if (bc > a && ev[bc] > ev[a]) {
                    float te = ev[a]; ev[a] = ev[bc]; ev[bc] = te;
                    #pragma unroll
                    for (int k = 0; k < 3; ++k) {
                        float tv = V[k][a]; V[k][a] = V[k][bc]; V[k][bc] = tv;
                    }
                }
        float U[3][3];
        #pragma unroll
        for (int j = 0; j < 3; ++j) {
            float sig = sqrtf(fmaxf(ev[j], 0.f));
            float inv = (sig > 1e-20f) ? (1.0f / sig) : 0.f;
            #pragma unroll
            for (int i = 0; i < 3; ++i)
                U[i][j] = (H[i][0] * V[0][j] + H[i][1] * V[1][j] + H[i][2] * V[2][j]) * inv;
        }
        auto det3 = [](float M[3][3]) {
            return M[0][0] * (M[1][1] * M[2][2] - M[1][2] * M[2][1])
                 - M[0][1] * (M[1][0] * M[2][2] - M[1][2] * M[2][0])
                 + M[0][2] * (M[1][0] * M[2][1] - M[1][1] * M[2][0]);
        };
        float sign = (det3(U) * det3(V) < 0.f) ? -1.f : 1.f;
        V[0][2] *= sign; V[1][2] *= sign; V[2][2] *= sign;
        float R[3][3];
        #pragma unroll
        for (int i = 0; i < 3; ++i)
            #pragma unroll
            for (int j = 0; j < 3; ++j)
                R[i][j] = V[i][0] * U[j][0] + V[i][1] * U[j][1] + V[i][2] * U[j][2];
        float tt[3];
        #pragma unroll
        for (int i = 0; i < 3; ++i)
            tt[i] = c2v[i] - (R[i][0] * c1v[0] + R[i][1] * c1v[1] + R[i][2] * c1v[2]);

        float* T = out + b * 16;
        #pragma unroll
        for (int i = 0; i < 3; ++i) {
            T[i * 4 + 0] = R[i][0];
            T[i * 4 + 1] = R[i][1];
            T[i * 4 + 2] = R[i][2];
            T[i * 4 + 3] = tt[i];
        }
        T[12] = 0.f; T[13] = 0.f; T[14] = 0.f; T[15] = 1.f;

        auto sgn = [](float x) { return x >= 0.f ? 1.f : -1.f; };
        float qw = 0.5f * sqrtf(fmaxf(1.f + R[0][0] + R[1][1] + R[2][2], 1e-12f));
        float qxq = 0.5f * sqrtf(fmaxf(1.f + R[0][0] - R[1][1] - R[2][2], 1e-12f)) * sgn(R[2][1] - R[1][2]);
        float qyq = 0.5f * sqrtf(fmaxf(1.f - R[0][0] + R[1][1] - R[2][2], 1e-12f)) * sgn(R[0][2] - R[2][0]);
        float qzq = 0.5f * sqrtf(fmaxf(1.f - R[0][0] - R[1][1] + R[2][2], 1e-12f)) * sgn(R[1][0] - R[0][1]);
        float* qo = out + BB * 16 + b * 4;
        qo[0] = qw; qo[1] = qxq; qo[2] = qyq; qo[3] = qzq;
        float* to = out + BB * 16 + BB * 4 + b * 3;
        to[0] = tt[0]; to[1] = tt[1]; to[2] = tt[2];
    }
}

// ---------------------------------------------------------------------------
extern "C" void kernel_launch(void* const* d_in, const int* in_sizes, int n_in,
                              void* d_out, int out_size) {
    const float* pc1 = (const float*)d_in[0];
    const float* pc2 = (const float*)d_in[1];
    float* out = (float*)d_out;

    cudaFuncSetAttribute(cpnet_rows, cudaFuncAttributeMaxDynamicSharedMemorySize,
                         2 * NP * (int)sizeof(ulonglong2));

    dim3 grid(NN / 32, BB);  // 128 x 8 = 1024 CTAs, 32 rows each (4 per warp)
    cpnet_rows<<<grid, 256, 2 * NP * sizeof(ulonglong2)>>>(pc1, pc2);
    cpnet_finalize<<<BB, FTH>>>(pc1, out);
}

// round 6
// speedup vs baseline: 1.3066x; 1.3066x over previous
#include <cuda_runtime.h>
#include <math.h>
#include <float.h>

#define BB 8
#define NN 4096
#define NP (NN / 2)  // element pairs

static __device__ __constant__ float kEPS = 1e-5f;
static __device__ __constant__ float kF2  = 2.8853900817779268f; // FACT * log2(e)
#define SKIP_LOG2 35.0f

// Scratch (device globals; no allocation allowed)
__device__ float g_pcn[BB][3][NN];
__device__ float g_dist[BB][NN];
__device__ unsigned g_cnt[BB];   // arrival counters (self-resetting)

typedef unsigned long long u64;

__device__ __forceinline__ float frcp(float x) {
    float r; asm("rcp.approx.f32 %0, %1;" : "=f"(r) : "f"(x)); return r;
}
__device__ __forceinline__ float fex2(float x) {
    float r; asm("ex2.approx.f32 %0, %1;" : "=f"(r) : "f"(x)); return r;
}
__device__ __forceinline__ u64 pk2(float lo, float hi) {
    u64 r; asm("mov.b64 %0, {%1, %2};" : "=l"(r) : "f"(lo), "f"(hi)); return r;
}
__device__ __forceinline__ void upk2(u64 v, float& lo, float& hi) {
    asm("mov.b64 {%0, %1}, %2;" : "=f"(lo), "=f"(hi) : "l"(v));
}
__device__ __forceinline__ u64 fma2(u64 a, u64 b, u64 c) {
    u64 d; asm("fma.rn.f32x2 %0, %1, %2, %3;" : "=l"(d) : "l"(a), "l"(b), "l"(c)); return d;
}
__device__ __forceinline__ u64 add2(u64 a, u64 b) {
    u64 d; asm("add.rn.f32x2 %0, %1, %2;" : "=l"(d) : "l"(a), "l"(b)); return d;
}

// ---------------------------------------------------------------------------
// Epilogue (executed by the LAST CTA of each batch): mean, moments, SVD, out.
// Uses the caller's dynamic smem (tile no longer needed) for reductions.
// ---------------------------------------------------------------------------
__device__ void batch_epilogue(int b, const float* __restrict__ p1,
                               float* __restrict__ out, void* smem_raw) {
    const int tid = threadIdx.x;
    const int lane = tid & 31;
    const int w = tid >> 5;  // 8 warps

    double* smMean = (double*)smem_raw;            // [8]
    float (*smP)[16] = (float(*)[16])(smMean + 8); // [8][16]
    double* smS = (double*)(smP + 8);              // [16]

    // ---- mean dist ----
    double sd = 0.0;
    #pragma unroll
    for (int k = 0; k < NN / 256; ++k) sd += (double)g_dist[b][k * 256 + tid];
    #pragma unroll
    for (int o = 16; o; o >>= 1) sd += __shfl_xor_sync(0xffffffffu, sd, o);
    if (lane == 0) smMean[w] = sd;
    __syncthreads();
    double ms = 0.0;
    #pragma unroll
    for (int i = 0; i < 8; ++i) ms += smMean[i];
    const float mean = (float)(ms * (1.0 / (double)NN));

    // ---- 16 uncentered moments ----
    float P[16];
    #pragma unroll
    for (int i = 0; i < 16; ++i) P[i] = 0.f;
    #pragma unroll
    for (int k = 0; k < NN / 256; ++k) {
        int n = k * 256 + tid;
        float dist = g_dist[b][n];
        float z = (dist - mean - kEPS) * 1e10f;
        float ind = 1.0f / (1.0f + __expf(z));
        float axx = p1[n], ayy = p1[NN + n], azz = p1[2 * NN + n];
        float bx = g_pcn[b][0][n], by = g_pcn[b][1][n], bz = g_pcn[b][2][n];
        float iax = ind * axx, iay = ind * ayy, iaz = ind * azz;
        P[0] += ind;
        P[1] += iax; P[2] += iay; P[3] += iaz;
        P[4] += ind * bx; P[5] += ind * by; P[6] += ind * bz;
        P[7]  += iax * bx; P[8]  += iax * by; P[9]  += iax * bz;
        P[10] += iay * bx; P[11] += iay * by; P[12] += iay * bz;
        P[13] += iaz * bx; P[14] += iaz * by; P[15] += iaz * bz;
    }
    #pragma unroll
    for (int o = 16; o; o >>= 1)
        #pragma unroll
        for (int i = 0; i < 16; ++i)
            P[i] += __shfl_xor_sync(0xffffffffu, P[i], o);
    if (lane == 0) {
        #pragma unroll
        for (int i = 0; i < 16; ++i) smP[w][i] = P[i];
    }
    __syncthreads();
    if (w == 0 && lane < 16) {
        double s = 0.0;
        #pragma unroll
        for (int ww = 0; ww < 8; ++ww) s += (double)smP[ww][lane];
        smS[lane] = s;
    }
    __syncthreads();

    if (tid != 0) return;

    double S[16];
    #pragma unroll
    for (int i = 0; i < 16; ++i) S[i] = smS[i];

    const double sw = S[0];
    const double inv_sw = 1.0 / sw;
    float c1v[3] = {(float)(S[1] * inv_sw), (float)(S[2] * inv_sw), (float)(S[3] * inv_sw)};
    float c2v[3] = {(float)(S[4] * inv_sw), (float)(S[5] * inv_sw), (float)(S[6] * inv_sw)};
    float H[3][3];
    #pragma unroll
    for (int i = 0; i < 3; ++i)
        #pragma unroll
        for (int j = 0; j < 3; ++j)
            H[i][j] = (float)(S[7 + i * 3 + j] - S[1 + i] * S[4 + j] * inv_sw);

    float G[3][3];
    #pragma unroll
    for (int i = 0; i < 3; ++i)
        #pragma unroll
        for (int j = 0; j < 3; ++j)
            G[i][j] = H[0][i] * H[0][j] + H[1][i] * H[1][j] + H[2][i] * H[2][j];
    float V[3][3] = {{1, 0, 0}, {0, 1, 0}, {0, 0, 1}};
    const int PP[3] = {0, 0, 1}, QQ[3] = {1, 2, 2};
    #pragma unroll
    for (int it = 0; it < 18; ++it) {
        int p = PP[it % 3], q = QQ[it % 3];
        float apq = G[p][q];
        if (fabsf(apq) > 1e-25f) {
            float theta = (G[q][q] - G[p][p]) / (2.0f * apq);
            float t = copysignf(1.0f, theta) / (fabsf(theta) + sqrtf(theta * theta + 1.0f));
            float c = rsqrtf(t * t + 1.0f);
            float sn = t * c;
            #pragma unroll
            for (int k = 0; k < 3; ++k) {
                float gkp = G[k][p], gkq = G[k][q];
                G[k][p] = c * gkp - sn * gkq;
                G[k][q] = sn * gkp + c * gkq;
            }
            #pragma unroll
            for (int k = 0; k < 3; ++k) {
                float gpk = G[p][k], gqk = G[q][k];
                G[p][k] = c * gpk - sn * gqk;
                G[q][k] = sn * gpk + c * gqk;
            }
            #pragma unroll
            for (int k = 0; k < 3; ++k) {
                float vkp = V[k][p], vkq = V[k][q];
                V[k][p] = c * vkp - sn * vkq;
                V[k][q] = sn * vkp + c * vkq;
            }
        }
    }
    float ev[3] = {G[0][0], G[1][1], G[2][2]};
    #pragma unroll
    for (int a = 0; a < 2; ++a)
        #pragma unroll
        for (int bc = 1; bc < 3; ++bc)
            if (bc > a && ev[bc] > ev[a]) {
                float te = ev[a]; ev[a] = ev[bc]; ev[bc] = te;
                #pragma unroll
                for (int k = 0; k < 3; ++k) {
                    float tv = V[k][a]; V[k][a] = V[k][bc]; V[k][bc] = tv;
                }
            }
    float U[3][3];
    #pragma unroll
    for (int j = 0; j < 3; ++j) {
        float sig = sqrtf(fmaxf(ev[j], 0.f));
        float inv = (sig > 1e-20f) ? (1.0f / sig) : 0.f;
        #pragma unroll
        for (int i = 0; i < 3; ++i)
            U[i][j] = (H[i][0] * V[0][j] + H[i][1] * V[1][j] + H[i][2] * V[2][j]) * inv;
    }
    auto det3 = [](float M[3][3]) {
        return M[0][0] * (M[1][1] * M[2][2] - M[1][2] * M[2][1])
             - M[0][1] * (M[1][0] * M[2][2] - M[1][2] * M[2][0])
             + M[0][2] * (M[1][0] * M[2][1] - M[1][1] * M[2][0]);
    };
    float sign = (det3(U) * det3(V) < 0.f) ? -1.f : 1.f;
    V[0][2] *= sign; V[1][2] *= sign; V[2][2] *= sign;
    float R[3][3];
    #pragma unroll
    for (int i = 0; i < 3; ++i)
        #pragma unroll
        for (int j = 0; j < 3; ++j)
            R[i][j] = V[i][0] * U[j][0] + V[i][1] * U[j][1] + V[i][2] * U[j][2];
    float tt[3];
    #pragma unroll
    for (int i = 0; i < 3; ++i)
        tt[i] = c2v[i] - (R[i][0] * c1v[0] + R[i][1] * c1v[1] + R[i][2] * c1v[2]);

    float* T = out + b * 16;
    #pragma unroll
    for (int i = 0; i < 3; ++i) {
        T[i * 4 + 0] = R[i][0];
        T[i * 4 + 1] = R[i][1];
        T[i * 4 + 2] = R[i][2];
        T[i * 4 + 3] = tt[i];
    }
    T[12] = 0.f; T[13] = 0.f; T[14] = 0.f; T[15] = 1.f;

    auto sgn = [](float x) { return x >= 0.f ? 1.f : -1.f; };
    float qw = 0.5f * sqrtf(fmaxf(1.f + R[0][0] + R[1][1] + R[2][2], 1e-12f));
    float qx = 0.5f * sqrtf(fmaxf(1.f + R[0][0] - R[1][1] - R[2][2], 1e-12f)) * sgn(R[2][1] - R[1][2]);
    float qy = 0.5f * sqrtf(fmaxf(1.f - R[0][0] + R[1][1] - R[2][2], 1e-12f)) * sgn(R[0][2] - R[2][0]);
    float qz = 0.5f * sqrtf(fmaxf(1.f - R[0][0] - R[1][1] + R[2][2], 1e-12f)) * sgn(R[1][0] - R[0][1]);
    float* qo = out + BB * 16 + b * 4;
    qo[0] = qw; qo[1] = qx; qo[2] = qy; qo[3] = qz;
    float* to = out + BB * 16 + BB * 4 + b * 3;
    to[0] = tt[0]; to[1] = tt[1]; to[2] = tt[2];
}

// ---------------------------------------------------------------------------
// Kernel: rows (R4 two-pass + vote-skip) with fused last-CTA epilogue.
// ---------------------------------------------------------------------------
__global__ void __launch_bounds__(256)
cpnet_rows(const float* __restrict__ pc1, const float* __restrict__ pc2,
           float* __restrict__ out) {
    extern __shared__ ulonglong2 smem[];
    ulonglong2* sXY = smem;        // 32KB
    ulonglong2* sZR = smem + NP;   // 32KB
    const int b = blockIdx.y;
    const float* p2 = pc2 + (size_t)b * 4 * NN;
    const float* p1 = pc1 + (size_t)b * 4 * NN;

    {
        const float2* px = (const float2*)p2;
        const float2* py = (const float2*)(p2 + NN);
        const float2* pz = (const float2*)(p2 + 2 * NN);
        for (int i = threadIdx.x; i < NP; i += blockDim.x) {
            float2 x = px[i], y = py[i], z = pz[i];
            float r0 = fmaf(z.x, z.x, fmaf(y.x, y.x, x.x * x.x));
            float r1 = fmaf(z.y, z.y, fmaf(y.y, y.y, x.y * x.y));
            sXY[i] = make_ulonglong2(pk2(x.x, x.y), pk2(y.x, y.y));
            sZR[i] = make_ulonglong2(pk2(z.x, z.y), pk2(r0, r1));
        }
    }
    __syncthreads();

    const int warp = threadIdx.x >> 5;
    const int lane = threadIdx.x & 31;
    const int n0 = (blockIdx.x << 5) + (warp << 2);  // 4 consecutive rows

    float qx[4], qy[4], qz[4];
    u64 nx2[4], ny2[4], nz2[4], rp2[4];
    #pragma unroll
    for (int r = 0; r < 4; ++r) {
        qx[r] = p1[n0 + r];
        qy[r] = p1[NN + n0 + r];
        qz[r] = p1[2 * NN + n0 + r];
        float rr = fmaf(qz[r], qz[r], fmaf(qy[r], qy[r], qx[r] * qx[r]));
        nx2[r] = pk2(-2.f * qx[r], -2.f * qx[r]);
        ny2[r] = pk2(-2.f * qy[r], -2.f * qy[r]);
        nz2[r] = pk2(-2.f * qz[r], -2.f * qz[r]);
        rp2[r] = pk2(rr, rr);
    }

    // ---- Pass 1: min squared distance per row ----
    float dm[4] = {FLT_MAX, FLT_MAX, FLT_MAX, FLT_MAX};
    #pragma unroll 4
    for (int p = lane; p < NP; p += 32) {
        ulonglong2 xy = sXY[p];
        ulonglong2 zr = sZR[p];
        #pragma unroll
        for (int r = 0; r < 4; ++r) {
            u64 d = fma2(nz2[r], zr.x, fma2(ny2[r], xy.y,
                         fma2(nx2[r], xy.x, add2(zr.y, rp2[r]))));
            float lo, hi; upk2(d, lo, hi);
            dm[r] = fminf(dm[r], fminf(lo, hi));
        }
    }
    #pragma unroll
    for (int o = 16; o; o >>= 1)
        #pragma unroll
        for (int r = 0; r < 4; ++r)
            dm[r] = fminf(dm[r], __shfl_xor_sync(0xffffffffu, dm[r], o));

    float cc[4], thr[4];
    u64 nc2[4];
    #pragma unroll
    for (int r = 0; r < 4; ++r) {
        cc[r] = kF2 * frcp(fmaxf(dm[r], kEPS));
        nc2[r] = pk2(-cc[r], -cc[r]);
        thr[r] = (cc[r] > SKIP_LOG2) ? kF2 * frcp(cc[r] - SKIP_LOG2) : FLT_MAX;
    }
    const u64 F2p = pk2(kF2, kF2);

    // ---- Pass 2: weights + accumulation with vote-skip ----
    u64 Zk[4] = {0, 0, 0, 0}, ax[4] = {0, 0, 0, 0};
    u64 ay[4] = {0, 0, 0, 0}, az[4] = {0, 0, 0, 0};
    for (int p = lane; p < NP; p += 32) {
        ulonglong2 xy = sXY[p];
        ulonglong2 zr = sZR[p];
        float dlo[4], dhi[4];
        bool f = false;
        #pragma unroll
        for (int r = 0; r < 4; ++r) {
            u64 d = fma2(nz2[r], zr.x, fma2(ny2[r], xy.y,
                         fma2(nx2[r], xy.x, add2(zr.y, rp2[r]))));
            upk2(d, dlo[r], dhi[r]);
            f |= (fminf(dlo[r], dhi[r]) <= thr[r]);
        }
        if (__any_sync(0xffffffffu, f)) {
            #pragma unroll
            for (int r = 0; r < 4; ++r) {
                float i0 = frcp(fmaxf(dlo[r], kEPS));
                float i1 = frcp(fmaxf(dhi[r], kEPS));
                u64 arg = fma2(pk2(i0, i1), F2p, nc2[r]);
                float g0, g1; upk2(arg, g0, g1);
                u64 w = pk2(fex2(g0), fex2(g1));
                Zk[r] = add2(Zk[r], w);
                ax[r] = fma2(w, xy.x, ax[r]);
                ay[r] = fma2(w, xy.y, ay[r]);
                az[r] = fma2(w, zr.x, az[r]);
            }
        }
    }

    float Zs[4], vx[4], vy[4], vz[4];
    #pragma unroll
    for (int r = 0; r < 4; ++r) {
        float lo, hi;
        upk2(Zk[r], lo, hi); Zs[r] = lo + hi;
        upk2(ax[r], lo, hi); vx[r] = lo + hi;
        upk2(ay[r], lo, hi); vy[r] = lo + hi;
        upk2(az[r], lo, hi); vz[r] = lo + hi;
    }
    #pragma unroll
    for (int o = 16; o; o >>= 1) {
        #pragma unroll
        for (int r = 0; r < 4; ++r) {
            Zs[r] += __shfl_xor_sync(0xffffffffu, Zs[r], o);
            vx[r] += __shfl_xor_sync(0xffffffffu, vx[r], o);
            vy[r] += __shfl_xor_sync(0xffffffffu, vy[r], o);
            vz[r] += __shfl_xor_sync(0xffffffffu, vz[r], o);
        }
    }

    if (lane == 0) {
        #pragma unroll
        for (int r = 0; r < 4; ++r) {
            float rz = 1.0f / Zs[r];
            float q0 = vx[r] * rz, q1 = vy[r] * rz, q2 = vz[r] * rz;
            float dx = qx[r] - q0, dy = qy[r] - q1, dz = qz[r] - q2;
            g_pcn[b][0][n0 + r] = q0;
            g_pcn[b][1][n0 + r] = q1;
            g_pcn[b][2][n0 + r] = q2;
            g_dist[b][n0 + r] = sqrtf(dx * dx + dy * dy + dz * dz);
        }
    }

    // ---- arrival + last-CTA epilogue ----
    __syncthreads();  // all warps' global stores issued
    __shared__ int isLast;
    if (threadIdx.x == 0) {
        __threadfence();  // release our batch's stores
        unsigned prev = atomicAdd(&g_cnt[b], 1u);
        isLast = (prev == (unsigned)(gridDim.x - 1));
        if (isLast) atomicExch(&g_cnt[b], 0u);  // self-reset for graph replay
    }
    __syncthreads();
    if (!isLast) return;
    __threadfence();  // acquire other CTAs' stores
    batch_epilogue(b, p1, out, (void*)smem);
}

// ---------------------------------------------------------------------------
extern "C" void kernel_launch(void* const* d_in, const int* in_sizes, int n_in,
                              void* d_out, int out_size) {
    const float* pc1 = (const float*)d_in[0];
    const float* pc2 = (const float*)d_in[1];
    float* out = (float*)d_out;

    cudaFuncSetAttribute(cpnet_rows, cudaFuncAttributeMaxDynamicSharedMemorySize,
                         2 * NP * (int)sizeof(ulonglong2));

    dim3 grid(NN / 32, BB);  // 128 x 8 = 1024 CTAs, 32 rows each (4 per warp)
    cpnet_rows<<<grid, 256, 2 * NP * sizeof(ulonglong2)>>>(pc1, pc2, out);
}